// round 13
// baseline (speedup 1.0000x reference)
#include <cuda_runtime.h>
#include <math.h>
#include <stdint.h>

// Problem constants
#define Bq   2
#define Sq   2048
#define HIDq 4096
#define Hq   32
#define KVq  8
#define Dq   128
#define Gq   (Hq / KVq)

// Scratch buffers (allocation-free rule: __device__ globals)
__device__ float g_projq[(size_t)Bq * Sq * Hq * Dq];   // raw Q projection [B*S, H*D]
__device__ float g_projk[(size_t)Bq * Sq * KVq * Dq];  // raw K projection
__device__ float g_projv[(size_t)Bq * Sq * KVq * Dq];  // raw V projection
__device__ float g_q[(size_t)Bq * Hq * Sq * Dq];       // [B,H,S,D]
__device__ float g_k[(size_t)Bq * KVq * Sq * Dq];      // [B,KV,S,D]
__device__ float g_v[(size_t)Bq * KVq * Sq * Dq];      // [B,KV,S,D]
__device__ float g_attn[(size_t)Bq * Sq * Hq * Dq];    // [B,S,H*D]

// ---------------------------------------------------------------------------
// TF32 tensor-core NT GEMM, double-buffered, 2 CTAs/SM.
// C[m,n] = sum_k A[m,k] * W[n,k]
// BM=BN=128, BK=16, 256 threads (8 warps), warp tile 64x32 via
// mma.sync.m16n8k8.tf32 (fp32 accumulate). GLD=20 (conflict-free frags,
// 16B-aligned rows).
// asel: 1 -> A = g_attn.
// csel: 0 -> Cparam, 1 -> g_projq, 2 -> g_projk, 3 -> g_projv.
// ---------------------------------------------------------------------------
__device__ __forceinline__ uint32_t f2tf32(float x) {
    uint32_t r;
    asm("cvt.rna.tf32.f32 %0, %1;" : "=r"(r) : "f"(x));
    return r;
}

__device__ __forceinline__ uint4 pack_tf32(float4 v) {
    uint4 r;
    r.x = f2tf32(v.x);
    r.y = f2tf32(v.y);
    r.z = f2tf32(v.z);
    r.w = f2tf32(v.w);
    return r;
}

__device__ __forceinline__ void mma_tf32(float& d0, float& d1, float& d2, float& d3,
                                         uint32_t a0, uint32_t a1, uint32_t a2, uint32_t a3,
                                         uint32_t b0, uint32_t b1) {
    asm volatile(
        "mma.sync.aligned.m16n8k8.row.col.f32.tf32.tf32.f32 "
        "{%0,%1,%2,%3}, {%4,%5,%6,%7}, {%8,%9}, {%0,%1,%2,%3};"
        : "+f"(d0), "+f"(d1), "+f"(d2), "+f"(d3)
        : "r"(a0), "r"(a1), "r"(a2), "r"(a3), "r"(b0), "r"(b1));
}

#define GLD 20

__global__ __launch_bounds__(256, 2)
void gemm_tc(const float* __restrict__ Aparam, const float* __restrict__ W,
             float* __restrict__ Cparam, int M, int N, int K,
             int asel, int csel)
{
    __shared__ uint32_t As[2][128 * GLD];
    __shared__ uint32_t Bs[2][128 * GLD];

    const float* A = (asel == 1) ? g_attn : Aparam;
    float* C = (csel == 0) ? Cparam
             : (csel == 1) ? g_projq
             : (csel == 2) ? g_projk : g_projv;

    const int tid  = threadIdx.x;
    const int lane = tid & 31;
    const int w    = tid >> 5;          // 0..7
    const int wm   = (w >> 2) * 64;     // warp row base: 0 or 64
    const int wn   = (w & 3) * 32;      // warp col base: 0,32,64,96
    const int gid  = lane >> 2;         // 0..7
    const int tig  = lane & 3;          // 0..3

    const int m0 = blockIdx.y * 128;
    const int n0 = blockIdx.x * 128;

    const int r0 = tid >> 2;            // 0..63
    const int c0 = (tid & 3) << 2;      // 0,4,8,12
    const int r1 = r0 + 64;             // 64..127

    const float* Arow0 = A + (size_t)(m0 + r0) * K + c0;
    const float* Arow1 = A + (size_t)(m0 + r1) * K + c0;
    const float* Wrow0 = W + (size_t)(n0 + r0) * K + c0;
    const float* Wrow1 = W + (size_t)(n0 + r1) * K + c0;

    float acc[4][4][4];
#pragma unroll
    for (int mt = 0; mt < 4; mt++)
#pragma unroll
        for (int nt = 0; nt < 4; nt++)
#pragma unroll
            for (int e = 0; e < 4; e++) acc[mt][nt][e] = 0.f;

    const int niter = K >> 4;

    // Prologue: stage 0
    {
        float4 a0v = *(const float4*)(Arow0);
        float4 a1v = *(const float4*)(Arow1);
        float4 b0v = *(const float4*)(Wrow0);
        float4 b1v = *(const float4*)(Wrow1);
        *(uint4*)&As[0][r0 * GLD + c0] = pack_tf32(a0v);
        *(uint4*)&As[0][r1 * GLD + c0] = pack_tf32(a1v);
        *(uint4*)&Bs[0][r0 * GLD + c0] = pack_tf32(b0v);
        *(uint4*)&Bs[0][r1 * GLD + c0] = pack_tf32(b1v);
    }
    __syncthreads();

    for (int i = 0; i < niter; i++) {
        const int cur = i & 1;
        const int nxt = cur ^ 1;

        float4 a0v, a1v, b0v, b1v;
        const bool more = (i + 1) < niter;
        if (more) {
            const int k0 = (i + 1) << 4;
            a0v = *(const float4*)(Arow0 + k0);
            a1v = *(const float4*)(Arow1 + k0);
            b0v = *(const float4*)(Wrow0 + k0);
            b1v = *(const float4*)(Wrow1 + k0);
        }

        const uint32_t* Ac = As[cur];
        const uint32_t* Bc = Bs[cur];
#pragma unroll
        for (int ks = 0; ks < 16; ks += 8) {
            uint32_t af[4][4];
#pragma unroll
            for (int mt = 0; mt < 4; mt++) {
                const int rbase = wm + mt * 16 + gid;
                af[mt][0] = Ac[(rbase    ) * GLD + ks + tig    ];
                af[mt][1] = Ac[(rbase + 8) * GLD + ks + tig    ];
                af[mt][2] = Ac[(rbase    ) * GLD + ks + tig + 4];
                af[mt][3] = Ac[(rbase + 8) * GLD + ks + tig + 4];
            }
            uint32_t bf[4][2];
#pragma unroll
            for (int nt = 0; nt < 4; nt++) {
                const int nrow = wn + nt * 8 + gid;
                bf[nt][0] = Bc[nrow * GLD + ks + tig    ];
                bf[nt][1] = Bc[nrow * GLD + ks + tig + 4];
            }
#pragma unroll
            for (int mt = 0; mt < 4; mt++)
#pragma unroll
                for (int nt = 0; nt < 4; nt++)
                    mma_tf32(acc[mt][nt][0], acc[mt][nt][1],
                             acc[mt][nt][2], acc[mt][nt][3],
                             af[mt][0], af[mt][1], af[mt][2], af[mt][3],
                             bf[nt][0], bf[nt][1]);
        }

        if (more) {
            *(uint4*)&As[nxt][r0 * GLD + c0] = pack_tf32(a0v);
            *(uint4*)&As[nxt][r1 * GLD + c0] = pack_tf32(a1v);
            *(uint4*)&Bs[nxt][r0 * GLD + c0] = pack_tf32(b0v);
            *(uint4*)&Bs[nxt][r1 * GLD + c0] = pack_tf32(b1v);
            __syncthreads();
        }
    }

#pragma unroll
    for (int mt = 0; mt < 4; mt++) {
#pragma unroll
        for (int nt = 0; nt < 4; nt++) {
            const int n = n0 + wn + nt * 8 + 2 * tig;
            const int mA = m0 + wm + mt * 16 + gid;
            float2 v01; v01.x = acc[mt][nt][0]; v01.y = acc[mt][nt][1];
            float2 v23; v23.x = acc[mt][nt][2]; v23.y = acc[mt][nt][3];
            *(float2*)(C + (size_t)mA * N + n)       = v01;
            *(float2*)(C + (size_t)(mA + 8) * N + n) = v23;
        }
    }
}

// ---------------------------------------------------------------------------
// Fused RoPE + transpose for Q, K, V in ONE launch.
// Q pairs: [0, QP)   from g_projq (rope) -> g_q   [B,H,S,D]
// K pairs: [QP, QP+KP) from g_projk (rope) -> g_k [B,KV,S,D]
// V pairs: [QP+KP, QP+2KP) from g_projv (copy) -> g_v
// ---------------------------------------------------------------------------
#define QPAIRS ((size_t)Bq * Sq * Hq * (Dq / 2))
#define KPAIRS ((size_t)Bq * Sq * KVq * (Dq / 2))

__global__ __launch_bounds__(256)
void rope_all(const float* __restrict__ cosp, const float* __restrict__ sinp)
{
    size_t idx = (size_t)blockIdx.x * blockDim.x + threadIdx.x;
    const float* src;
    float* dst;
    int Hh, dorope;
    if (idx < QPAIRS) {
        src = g_projq; dst = g_q; Hh = Hq; dorope = 1;
    } else if (idx < QPAIRS + KPAIRS) {
        idx -= QPAIRS;
        src = g_projk; dst = g_k; Hh = KVq; dorope = 1;
    } else if (idx < QPAIRS + 2 * KPAIRS) {
        idx -= QPAIRS + KPAIRS;
        src = g_projv; dst = g_v; Hh = KVq; dorope = 0;
    } else {
        return;
    }

    const int dpair = (int)(idx % (Dq / 2));
    size_t rest = idx / (Dq / 2);
    const int hh = (int)(rest % Hh);  rest /= Hh;
    const int s  = (int)(rest % Sq);
    const int b  = (int)(rest / Sq);
    const int d  = dpair * 2;

    const size_t srcix = ((size_t)(b * Sq + s) * Hh + hh) * Dq + d;
    float v0 = src[srcix];
    float v1 = src[srcix + 1];
    if (dorope) {
        const float c  = cosp[s * Dq + d];
        const float sn = sinp[s * Dq + d];
        const float t0 = v0 * c - v1 * sn;
        const float t1 = v1 * c + v0 * sn;
        v0 = t0; v1 = t1;
    }
    const size_t o = (((size_t)b * Hh + hh) * Sq + s) * Dq + d;
    dst[o]     = v0;
    dst[o + 1] = v1;
}

// ---------------------------------------------------------------------------
// Flash attention v3 (unchanged - PASSING). LDP=130 (rows are 128 wide).
// ---------------------------------------------------------------------------
#define LDP 130
#define FLASH_FLOATS (64 * LDP + 32 * LDP + 32 * 128)

__global__ __launch_bounds__(256)
void flash_v3()
{
    extern __shared__ float sm[];
    float* Qs = sm;                  // [64][LDP]
    float* Ks = Qs + 64 * LDP;       // [32][LDP]; after scores reused as P[c][r]
    float* Vs = Ks + 32 * LDP;       // [32][128]

    const int qb = blockIdx.x;
    const int h  = blockIdx.y;
    const int b  = blockIdx.z;
    const int kh = h / Gq;
    const int tid = threadIdx.x;
    const int r = tid >> 2;
    const int q = tid & 3;
    const float scale = 0.08838834764831845f;

    const float* Qg = g_q + (((size_t)b * Hq  + h ) * Sq + (size_t)qb * 64) * Dq;
    const float* Kg = g_k + (((size_t)b * KVq + kh) * Sq) * Dq;
    const float* Vg = g_v + (((size_t)b * KVq + kh) * Sq) * Dq;

#pragma unroll
    for (int i = 0; i < 8; i++) {
        const int idx = tid + i * 256;
        const int rr = idx >> 5;
        const int c4 = (idx & 31) << 2;
        float4 v = *(const float4*)(Qg + rr * Dq + c4);
        Qs[rr * LDP + c4 + 0] = v.x;
        Qs[rr * LDP + c4 + 1] = v.y;
        Qs[rr * LDP + c4 + 2] = v.z;
        Qs[rr * LDP + c4 + 3] = v.w;
    }

    float m_i = -INFINITY;
    float l_i = 0.f;
    float o[32];
#pragma unroll
    for (int j = 0; j < 32; j++) o[j] = 0.f;

    const int qr = qb * 64 + r;
    const int ntiles = 2 * qb + 2;

    for (int cb = 0; cb < ntiles; cb++) {
        __syncthreads();
#pragma unroll
        for (int i = 0; i < 4; i++) {
            const int idx = tid + i * 256;
            const int rr = idx >> 5;
            const int c4 = (idx & 31) << 2;
            float4 kv = *(const float4*)(Kg + (size_t)(cb * 32 + rr) * Dq + c4);
            Ks[rr * LDP + c4 + 0] = kv.x;
            Ks[rr * LDP + c4 + 1] = kv.y;
            Ks[rr * LDP + c4 + 2] = kv.z;
            Ks[rr * LDP + c4 + 3] = kv.w;
            float4 vv = *(const float4*)(Vg + (size_t)(cb * 32 + rr) * Dq + c4);
            *(float4*)(Vs + rr * 128 + c4) = vv;
        }
        __syncthreads();

        float s8[8];
#pragma unroll
        for (int j = 0; j < 8; j++) s8[j] = 0.f;
        const float* qrow = Qs + r * LDP;
#pragma unroll 4
        for (int k = 0; k < 128; k++) {
            const float qv = qrow[k];
#pragma unroll
            for (int j = 0; j < 8; j++)
                s8[j] += qv * Ks[(q * 8 + j) * LDP + k];
        }
        __syncthreads();

        float mx = -INFINITY;
#pragma unroll
        for (int j = 0; j < 8; j++) {
            const int kc = cb * 32 + q * 8 + j;
            s8[j] = (kc <= qr) ? s8[j] * scale : -INFINITY;
            mx = fmaxf(mx, s8[j]);
        }
        mx = fmaxf(mx, __shfl_xor_sync(0xffffffffu, mx, 1));
        mx = fmaxf(mx, __shfl_xor_sync(0xffffffffu, mx, 2));
        const float m_new = fmaxf(m_i, mx);
        const float corr  = __expf(m_i - m_new);
        float lsum = 0.f;
#pragma unroll
        for (int j = 0; j < 8; j++) {
            s8[j] = __expf(s8[j] - m_new);
            lsum += s8[j];
        }
        lsum += __shfl_xor_sync(0xffffffffu, lsum, 1);
        lsum += __shfl_xor_sync(0xffffffffu, lsum, 2);
        l_i = l_i * corr + lsum;
        m_i = m_new;
#pragma unroll
        for (int j = 0; j < 32; j++) o[j] *= corr;
#pragma unroll
        for (int j = 0; j < 8; j++)
            Ks[(q * 8 + j) * LDP + r] = s8[j];
        __syncthreads();

        for (int c = 0; c < 32; c++) {
            const float pv = Ks[c * LDP + r];
            const float* vrow = Vs + c * 128 + q * 4;
#pragma unroll
            for (int j = 0; j < 8; j++) {
                float4 v4 = *(const float4*)(vrow + j * 16);
                o[j * 4 + 0] += pv * v4.x;
                o[j * 4 + 1] += pv * v4.y;
                o[j * 4 + 2] += pv * v4.z;
                o[j * 4 + 3] += pv * v4.w;
            }
        }
    }

    const float inv = 1.f / l_i;
    float* og = g_attn + ((size_t)(b * Sq + qr) * Hq + h) * Dq + q * 4;
#pragma unroll
    for (int j = 0; j < 8; j++) {
        float4 v;
        v.x = o[j * 4 + 0] * inv;
        v.y = o[j * 4 + 1] * inv;
        v.z = o[j * 4 + 2] * inv;
        v.w = o[j * 4 + 3] * inv;
        *(float4*)(og + j * 16) = v;
    }
}

// ---------------------------------------------------------------------------
// Launcher. Order: gemm_q(0), gemm_k(1), gemm_v(2), rope_all(3), flash(4),
// gemm_o(5)  -> ncu -s 5 -c 1 captures gemm_o next round.
// ---------------------------------------------------------------------------
extern "C" void kernel_launch(void* const* d_in, const int* in_sizes, int n_in,
                              void* d_out, int out_size)
{
    const float *hs, *cosp, *sinp, *wq, *wk, *wv, *wo;
    if (in_sizes[0] == Bq * Sq * HIDq) {
        hs   = (const float*)d_in[0];
        cosp = (const float*)d_in[1];
        sinp = (const float*)d_in[2];
        wq   = (const float*)d_in[3];
        wk   = (const float*)d_in[4];
        wv   = (const float*)d_in[5];
        wo   = (const float*)d_in[6];
    } else {  // alphabetical fallback
        cosp = (const float*)d_in[0];
        hs   = (const float*)d_in[1];
        sinp = (const float*)d_in[2];
        wk   = (const float*)d_in[3];
        wo   = (const float*)d_in[4];
        wq   = (const float*)d_in[5];
        wv   = (const float*)d_in[6];
    }
    float* out = (float*)d_out;

    const dim3 blk(256);
    const int M = Bq * Sq;          // 4096
    const int NQ = Hq * Dq;         // 4096
    const int NKV = KVq * Dq;       // 1024

    // Projections (independent buffers -> can run back to back)
    gemm_tc<<<dim3(NQ / 128, M / 128), blk>>>(hs, wq, nullptr, M, NQ, HIDq, 0, 1);
    gemm_tc<<<dim3(NKV / 128, M / 128), blk>>>(hs, wk, nullptr, M, NKV, HIDq, 0, 2);
    gemm_tc<<<dim3(NKV / 128, M / 128), blk>>>(hs, wv, nullptr, M, NKV, HIDq, 0, 3);

    // Fused RoPE/transpose for Q,K,V
    {
        size_t total = QPAIRS + 2 * KPAIRS;
        rope_all<<<(unsigned)((total + 255) / 256), 256>>>(cosp, sinp);
    }

    // Flash attention v3 -> g_attn
    const int smem_bytes = FLASH_FLOATS * (int)sizeof(float);  // 66,304
    cudaFuncSetAttribute(flash_v3, cudaFuncAttributeMaxDynamicSharedMemorySize,
                         smem_bytes);
    flash_v3<<<dim3(Sq / 64, Hq, Bq), blk, smem_bytes>>>();

    // Output projection: out = g_attn @ wo^T
    gemm_tc<<<dim3(HIDq / 128, M / 128), blk>>>(nullptr, wo, out, M, HIDq, NQ, 1, 0);
}

// round 14
// speedup vs baseline: 1.0269x; 1.0269x over previous
#include <cuda_runtime.h>
#include <math.h>
#include <stdint.h>

// Problem constants
#define Bq   2
#define Sq   2048
#define HIDq 4096
#define Hq   32
#define KVq  8
#define Dq   128
#define Gq   (Hq / KVq)

// Scratch buffers (allocation-free rule: __device__ globals)
__device__ float g_projq[(size_t)Bq * Sq * Hq * Dq];   // raw Q projection [B*S, H*D]
__device__ float g_projk[(size_t)Bq * Sq * KVq * Dq];  // raw K projection
__device__ float g_projv[(size_t)Bq * Sq * KVq * Dq];  // raw V projection
__device__ float g_q[(size_t)Bq * Hq * Sq * Dq];       // [B,H,S,D]
__device__ float g_k[(size_t)Bq * KVq * Sq * Dq];      // [B,KV,S,D]
__device__ float g_v[(size_t)Bq * KVq * Sq * Dq];      // [B,KV,S,D]
__device__ float g_attn[(size_t)Bq * Sq * Hq * Dq];    // [B,S,H*D]

// ---------------------------------------------------------------------------
// TF32 tensor-core NT GEMM with 3-stage cp.async pipeline.
// C[m,n] = sum_k A[m,k] * W[n,k]
// BM=BN=128, BK=16, 256 threads (8 warps), warp tile 64x32,
// mma.sync.m16n8k8.tf32 (fp32 accumulate).
// Smem holds raw fp32 (cp.async lands directly); cvt.rna.tf32 at fragment
// load (same arithmetic as before => bit-identical result).
// GLD=20: conflict-free fragment LDS + rows 80B (16B-aligned for cp.async).
// ---------------------------------------------------------------------------
__device__ __forceinline__ uint32_t f2tf32(float x) {
    uint32_t r;
    asm("cvt.rna.tf32.f32 %0, %1;" : "=r"(r) : "f"(x));
    return r;
}

__device__ __forceinline__ void mma_tf32(float& d0, float& d1, float& d2, float& d3,
                                         uint32_t a0, uint32_t a1, uint32_t a2, uint32_t a3,
                                         uint32_t b0, uint32_t b1) {
    asm volatile(
        "mma.sync.aligned.m16n8k8.row.col.f32.tf32.tf32.f32 "
        "{%0,%1,%2,%3}, {%4,%5,%6,%7}, {%8,%9}, {%0,%1,%2,%3};"
        : "+f"(d0), "+f"(d1), "+f"(d2), "+f"(d3)
        : "r"(a0), "r"(a1), "r"(a2), "r"(a3), "r"(b0), "r"(b1));
}

__device__ __forceinline__ void cp16(void* dst, const void* src) {
    uint32_t d = (uint32_t)__cvta_generic_to_shared(dst);
    asm volatile("cp.async.ca.shared.global [%0], [%1], 16;" :: "r"(d), "l"(src));
}

#define GLD     20
#define STAGES  3
#define TILE_W  (128 * GLD)                       // floats per tile
#define GEMM_SMEM_BYTES (STAGES * 2 * TILE_W * 4) // 61,440

__global__ __launch_bounds__(256, 2)
void gemm_tc(const float* __restrict__ Aparam, const float* __restrict__ W,
             float* __restrict__ Cparam, int M, int N, int K,
             int asel, int csel)
{
    extern __shared__ float smem[];
    float* Asm = smem;                    // [STAGES][TILE_W]
    float* Bsm = smem + STAGES * TILE_W;  // [STAGES][TILE_W]

    const float* A = (asel == 1) ? g_attn : Aparam;
    float* C = (csel == 0) ? Cparam
             : (csel == 1) ? g_projq
             : (csel == 2) ? g_projk : g_projv;

    const int tid  = threadIdx.x;
    const int lane = tid & 31;
    const int w    = tid >> 5;          // 0..7
    const int wm   = (w >> 2) * 64;     // warp row base: 0 or 64
    const int wn   = (w & 3) * 32;      // warp col base: 0,32,64,96
    const int gid  = lane >> 2;         // 0..7
    const int tig  = lane & 3;          // 0..3

    const int m0 = blockIdx.y * 128;
    const int n0 = blockIdx.x * 128;

    // cp.async mapping: thread t copies 16B chunks for rows r0 and r0+64,
    // column chunk c0 (floats). Row stride GLD*4=80B is 16B-aligned.
    const int r0 = tid >> 2;            // 0..63
    const int c0 = (tid & 3) << 2;      // 0,4,8,12
    const int r1 = r0 + 64;             // 64..127

    const float* Arow0 = A + (size_t)(m0 + r0) * K + c0;
    const float* Arow1 = A + (size_t)(m0 + r1) * K + c0;
    const float* Wrow0 = W + (size_t)(n0 + r0) * K + c0;
    const float* Wrow1 = W + (size_t)(n0 + r1) * K + c0;

    float acc[4][4][4];
#pragma unroll
    for (int mt = 0; mt < 4; mt++)
#pragma unroll
        for (int nt = 0; nt < 4; nt++)
#pragma unroll
            for (int e = 0; e < 4; e++) acc[mt][nt][e] = 0.f;

    const int niter = K >> 4;

    // Prologue: stages 0 and 1 in flight.
    {
        float* Ad = Asm; float* Bd = Bsm;
        cp16(Ad + r0 * GLD + c0, Arow0);
        cp16(Ad + r1 * GLD + c0, Arow1);
        cp16(Bd + r0 * GLD + c0, Wrow0);
        cp16(Bd + r1 * GLD + c0, Wrow1);
        asm volatile("cp.async.commit_group;");
        Ad = Asm + TILE_W; Bd = Bsm + TILE_W;
        cp16(Ad + r0 * GLD + c0, Arow0 + 16);
        cp16(Ad + r1 * GLD + c0, Arow1 + 16);
        cp16(Bd + r0 * GLD + c0, Wrow0 + 16);
        cp16(Bd + r1 * GLD + c0, Wrow1 + 16);
        asm volatile("cp.async.commit_group;");
    }

    for (int i = 0; i < niter; i++) {
        // Stage i's group done once <=1 group pending (prologue=2 + 1/iter).
        asm volatile("cp.async.wait_group 1;");
        __syncthreads();   // stage i visible; all warps done with stage i-1

        // Issue loads for stage i+2 into the slot stage i-1 used.
        if (i + 2 < niter) {
            const int s = (i + 2) % STAGES;
            const int k0 = (i + 2) << 4;
            float* Ad = Asm + s * TILE_W;
            float* Bd = Bsm + s * TILE_W;
            cp16(Ad + r0 * GLD + c0, Arow0 + k0);
            cp16(Ad + r1 * GLD + c0, Arow1 + k0);
            cp16(Bd + r0 * GLD + c0, Wrow0 + k0);
            cp16(Bd + r1 * GLD + c0, Wrow1 + k0);
        }
        asm volatile("cp.async.commit_group;");  // unconditional: keeps count exact

        const float* Ac = Asm + (i % STAGES) * TILE_W;
        const float* Bc = Bsm + (i % STAGES) * TILE_W;
#pragma unroll
        for (int ks = 0; ks < 16; ks += 8) {
            uint32_t af[4][4];
#pragma unroll
            for (int mt = 0; mt < 4; mt++) {
                const int rbase = wm + mt * 16 + gid;
                af[mt][0] = f2tf32(Ac[(rbase    ) * GLD + ks + tig    ]);
                af[mt][1] = f2tf32(Ac[(rbase + 8) * GLD + ks + tig    ]);
                af[mt][2] = f2tf32(Ac[(rbase    ) * GLD + ks + tig + 4]);
                af[mt][3] = f2tf32(Ac[(rbase + 8) * GLD + ks + tig + 4]);
            }
            uint32_t bf[4][2];
#pragma unroll
            for (int nt = 0; nt < 4; nt++) {
                const int nrow = wn + nt * 8 + gid;
                bf[nt][0] = f2tf32(Bc[nrow * GLD + ks + tig    ]);
                bf[nt][1] = f2tf32(Bc[nrow * GLD + ks + tig + 4]);
            }
#pragma unroll
            for (int mt = 0; mt < 4; mt++)
#pragma unroll
                for (int nt = 0; nt < 4; nt++)
                    mma_tf32(acc[mt][nt][0], acc[mt][nt][1],
                             acc[mt][nt][2], acc[mt][nt][3],
                             af[mt][0], af[mt][1], af[mt][2], af[mt][3],
                             bf[nt][0], bf[nt][1]);
        }
    }

    // Epilogue: (row = gid | gid+8, col = 2*tig | 2*tig+1) per 16x8 subtile.
#pragma unroll
    for (int mt = 0; mt < 4; mt++) {
#pragma unroll
        for (int nt = 0; nt < 4; nt++) {
            const int n = n0 + wn + nt * 8 + 2 * tig;
            const int mA = m0 + wm + mt * 16 + gid;
            float2 v01; v01.x = acc[mt][nt][0]; v01.y = acc[mt][nt][1];
            float2 v23; v23.x = acc[mt][nt][2]; v23.y = acc[mt][nt][3];
            *(float2*)(C + (size_t)mA * N + n)       = v01;
            *(float2*)(C + (size_t)(mA + 8) * N + n) = v23;
        }
    }
}

// ---------------------------------------------------------------------------
// Fused RoPE + transpose for Q, K, V in ONE launch (unchanged - PASSING)
// ---------------------------------------------------------------------------
#define QPAIRS ((size_t)Bq * Sq * Hq * (Dq / 2))
#define KPAIRS ((size_t)Bq * Sq * KVq * (Dq / 2))

__global__ __launch_bounds__(256)
void rope_all(const float* __restrict__ cosp, const float* __restrict__ sinp)
{
    size_t idx = (size_t)blockIdx.x * blockDim.x + threadIdx.x;
    const float* src;
    float* dst;
    int Hh, dorope;
    if (idx < QPAIRS) {
        src = g_projq; dst = g_q; Hh = Hq; dorope = 1;
    } else if (idx < QPAIRS + KPAIRS) {
        idx -= QPAIRS;
        src = g_projk; dst = g_k; Hh = KVq; dorope = 1;
    } else if (idx < QPAIRS + 2 * KPAIRS) {
        idx -= QPAIRS + KPAIRS;
        src = g_projv; dst = g_v; Hh = KVq; dorope = 0;
    } else {
        return;
    }

    const int dpair = (int)(idx % (Dq / 2));
    size_t rest = idx / (Dq / 2);
    const int hh = (int)(rest % Hh);  rest /= Hh;
    const int s  = (int)(rest % Sq);
    const int b  = (int)(rest / Sq);
    const int d  = dpair * 2;

    const size_t srcix = ((size_t)(b * Sq + s) * Hh + hh) * Dq + d;
    float v0 = src[srcix];
    float v1 = src[srcix + 1];
    if (dorope) {
        const float c  = cosp[s * Dq + d];
        const float sn = sinp[s * Dq + d];
        const float t0 = v0 * c - v1 * sn;
        const float t1 = v1 * c + v0 * sn;
        v0 = t0; v1 = t1;
    }
    const size_t o = (((size_t)b * Hh + hh) * Sq + s) * Dq + d;
    dst[o]     = v0;
    dst[o + 1] = v1;
}

// ---------------------------------------------------------------------------
// Flash attention v3 (unchanged - PASSING). LDP=130 (rows are 128 wide).
// ---------------------------------------------------------------------------
#define LDP 130
#define FLASH_FLOATS (64 * LDP + 32 * LDP + 32 * 128)

__global__ __launch_bounds__(256)
void flash_v3()
{
    extern __shared__ float sm[];
    float* Qs = sm;                  // [64][LDP]
    float* Ks = Qs + 64 * LDP;       // [32][LDP]; after scores reused as P[c][r]
    float* Vs = Ks + 32 * LDP;       // [32][128]

    const int qb = blockIdx.x;
    const int h  = blockIdx.y;
    const int b  = blockIdx.z;
    const int kh = h / Gq;
    const int tid = threadIdx.x;
    const int r = tid >> 2;
    const int q = tid & 3;
    const float scale = 0.08838834764831845f;

    const float* Qg = g_q + (((size_t)b * Hq  + h ) * Sq + (size_t)qb * 64) * Dq;
    const float* Kg = g_k + (((size_t)b * KVq + kh) * Sq) * Dq;
    const float* Vg = g_v + (((size_t)b * KVq + kh) * Sq) * Dq;

#pragma unroll
    for (int i = 0; i < 8; i++) {
        const int idx = tid + i * 256;
        const int rr = idx >> 5;
        const int c4 = (idx & 31) << 2;
        float4 v = *(const float4*)(Qg + rr * Dq + c4);
        Qs[rr * LDP + c4 + 0] = v.x;
        Qs[rr * LDP + c4 + 1] = v.y;
        Qs[rr * LDP + c4 + 2] = v.z;
        Qs[rr * LDP + c4 + 3] = v.w;
    }

    float m_i = -INFINITY;
    float l_i = 0.f;
    float o[32];
#pragma unroll
    for (int j = 0; j < 32; j++) o[j] = 0.f;

    const int qr = qb * 64 + r;
    const int ntiles = 2 * qb + 2;

    for (int cb = 0; cb < ntiles; cb++) {
        __syncthreads();
#pragma unroll
        for (int i = 0; i < 4; i++) {
            const int idx = tid + i * 256;
            const int rr = idx >> 5;
            const int c4 = (idx & 31) << 2;
            float4 kv = *(const float4*)(Kg + (size_t)(cb * 32 + rr) * Dq + c4);
            Ks[rr * LDP + c4 + 0] = kv.x;
            Ks[rr * LDP + c4 + 1] = kv.y;
            Ks[rr * LDP + c4 + 2] = kv.z;
            Ks[rr * LDP + c4 + 3] = kv.w;
            float4 vv = *(const float4*)(Vg + (size_t)(cb * 32 + rr) * Dq + c4);
            *(float4*)(Vs + rr * 128 + c4) = vv;
        }
        __syncthreads();

        float s8[8];
#pragma unroll
        for (int j = 0; j < 8; j++) s8[j] = 0.f;
        const float* qrow = Qs + r * LDP;
#pragma unroll 4
        for (int k = 0; k < 128; k++) {
            const float qv = qrow[k];
#pragma unroll
            for (int j = 0; j < 8; j++)
                s8[j] += qv * Ks[(q * 8 + j) * LDP + k];
        }
        __syncthreads();

        float mx = -INFINITY;
#pragma unroll
        for (int j = 0; j < 8; j++) {
            const int kc = cb * 32 + q * 8 + j;
            s8[j] = (kc <= qr) ? s8[j] * scale : -INFINITY;
            mx = fmaxf(mx, s8[j]);
        }
        mx = fmaxf(mx, __shfl_xor_sync(0xffffffffu, mx, 1));
        mx = fmaxf(mx, __shfl_xor_sync(0xffffffffu, mx, 2));
        const float m_new = fmaxf(m_i, mx);
        const float corr  = __expf(m_i - m_new);
        float lsum = 0.f;
#pragma unroll
        for (int j = 0; j < 8; j++) {
            s8[j] = __expf(s8[j] - m_new);
            lsum += s8[j];
        }
        lsum += __shfl_xor_sync(0xffffffffu, lsum, 1);
        lsum += __shfl_xor_sync(0xffffffffu, lsum, 2);
        l_i = l_i * corr + lsum;
        m_i = m_new;
#pragma unroll
        for (int j = 0; j < 32; j++) o[j] *= corr;
#pragma unroll
        for (int j = 0; j < 8; j++)
            Ks[(q * 8 + j) * LDP + r] = s8[j];
        __syncthreads();

        for (int c = 0; c < 32; c++) {
            const float pv = Ks[c * LDP + r];
            const float* vrow = Vs + c * 128 + q * 4;
#pragma unroll
            for (int j = 0; j < 8; j++) {
                float4 v4 = *(const float4*)(vrow + j * 16);
                o[j * 4 + 0] += pv * v4.x;
                o[j * 4 + 1] += pv * v4.y;
                o[j * 4 + 2] += pv * v4.z;
                o[j * 4 + 3] += pv * v4.w;
            }
        }
    }

    const float inv = 1.f / l_i;
    float* og = g_attn + ((size_t)(b * Sq + qr) * Hq + h) * Dq + q * 4;
#pragma unroll
    for (int j = 0; j < 8; j++) {
        float4 v;
        v.x = o[j * 4 + 0] * inv;
        v.y = o[j * 4 + 1] * inv;
        v.z = o[j * 4 + 2] * inv;
        v.w = o[j * 4 + 3] * inv;
        *(float4*)(og + j * 16) = v;
    }
}

// ---------------------------------------------------------------------------
// Launcher
// ---------------------------------------------------------------------------
extern "C" void kernel_launch(void* const* d_in, const int* in_sizes, int n_in,
                              void* d_out, int out_size)
{
    const float *hs, *cosp, *sinp, *wq, *wk, *wv, *wo;
    if (in_sizes[0] == Bq * Sq * HIDq) {
        hs   = (const float*)d_in[0];
        cosp = (const float*)d_in[1];
        sinp = (const float*)d_in[2];
        wq   = (const float*)d_in[3];
        wk   = (const float*)d_in[4];
        wv   = (const float*)d_in[5];
        wo   = (const float*)d_in[6];
    } else {  // alphabetical fallback
        cosp = (const float*)d_in[0];
        hs   = (const float*)d_in[1];
        sinp = (const float*)d_in[2];
        wk   = (const float*)d_in[3];
        wo   = (const float*)d_in[4];
        wq   = (const float*)d_in[5];
        wv   = (const float*)d_in[6];
    }
    float* out = (float*)d_out;

    const dim3 blk(256);
    const int M = Bq * Sq;          // 4096
    const int NQ = Hq * Dq;         // 4096
    const int NKV = KVq * Dq;       // 1024

    cudaFuncSetAttribute(gemm_tc, cudaFuncAttributeMaxDynamicSharedMemorySize,
                         GEMM_SMEM_BYTES);

    // Projections
    gemm_tc<<<dim3(NQ / 128, M / 128), blk, GEMM_SMEM_BYTES>>>(hs, wq, nullptr, M, NQ, HIDq, 0, 1);
    gemm_tc<<<dim3(NKV / 128, M / 128), blk, GEMM_SMEM_BYTES>>>(hs, wk, nullptr, M, NKV, HIDq, 0, 2);
    gemm_tc<<<dim3(NKV / 128, M / 128), blk, GEMM_SMEM_BYTES>>>(hs, wv, nullptr, M, NKV, HIDq, 0, 3);

    // Fused RoPE/transpose for Q,K,V
    {
        size_t total = QPAIRS + 2 * KPAIRS;
        rope_all<<<(unsigned)((total + 255) / 256), 256>>>(cosp, sinp);
    }

    // Flash attention v3 -> g_attn
    const int smem_bytes = FLASH_FLOATS * (int)sizeof(float);  // 66,304
    cudaFuncSetAttribute(flash_v3, cudaFuncAttributeMaxDynamicSharedMemorySize,
                         smem_bytes);
    flash_v3<<<dim3(Sq / 64, Hq, Bq), blk, smem_bytes>>>();

    // Output projection: out = g_attn @ wo^T
    gemm_tc<<<dim3(HIDq / 128, M / 128), blk, GEMM_SMEM_BYTES>>>(nullptr, wo, out, M, HIDq, NQ, 1, 0);
}

// round 15
// speedup vs baseline: 1.1503x; 1.1202x over previous
#include <cuda_runtime.h>
#include <cuda_fp16.h>
#include <math.h>
#include <stdint.h>

// Problem constants
#define Bq   2
#define Sq   2048
#define HIDq 4096
#define Hq   32
#define KVq  8
#define Dq   128
#define Gq   (Hq / KVq)

// Scratch buffers (allocation-free rule: __device__ globals)
__device__ __half g_hsh[(size_t)Bq * Sq * HIDq];        // fp16 hidden_states
__device__ __half g_wqh[(size_t)Hq * Dq * HIDq];        // fp16 wq
__device__ __half g_wkh[(size_t)KVq * Dq * HIDq];       // fp16 wk
__device__ __half g_wvh[(size_t)KVq * Dq * HIDq];       // fp16 wv
__device__ __half g_woh[(size_t)HIDq * Hq * Dq];        // fp16 wo
__device__ __half g_attnh[(size_t)Bq * Sq * Hq * Dq];   // fp16 attn out [B,S,H*D]
__device__ float g_projq[(size_t)Bq * Sq * Hq * Dq];    // raw Q projection
__device__ float g_projk[(size_t)Bq * Sq * KVq * Dq];   // raw K projection
__device__ float g_projv[(size_t)Bq * Sq * KVq * Dq];   // raw V projection
__device__ float g_q[(size_t)Bq * Hq * Sq * Dq];        // [B,H,S,D]
__device__ float g_k[(size_t)Bq * KVq * Sq * Dq];       // [B,KV,S,D]
__device__ float g_v[(size_t)Bq * KVq * Sq * Dq];       // [B,KV,S,D]

// ---------------------------------------------------------------------------
// fp32 -> fp16 conversion (vectorized). dsel: 0 hs, 1 wq, 2 wk, 3 wv, 4 wo.
// ---------------------------------------------------------------------------
__global__ __launch_bounds__(256)
void to_half(const float4* __restrict__ src, int dsel, size_t n4)
{
    size_t i = (size_t)blockIdx.x * blockDim.x + threadIdx.x;
    if (i >= n4) return;
    __half* dst = (dsel == 0) ? g_hsh
                : (dsel == 1) ? g_wqh
                : (dsel == 2) ? g_wkh
                : (dsel == 3) ? g_wvh : g_woh;
    float4 v = src[i];
    __half2* d2 = (__half2*)(dst + i * 4);
    d2[0] = __floats2half2_rn(v.x, v.y);
    d2[1] = __floats2half2_rn(v.z, v.w);
}

// ---------------------------------------------------------------------------
// fp16 tensor-core NT GEMM with 3-stage cp.async pipeline.
// C[m,n] = sum_k A[m,k] * W[n,k], fp32 accumulate.
// BM=BN=128, BK=32, 256 threads (8 warps), warp tile 64x32,
// mma.sync.m16n8k16.f16 (2 k-steps per iter). niter = K/32.
// Smem rows: 32 halves padded to LDH=40 (80B, 16B-aligned, conflict-free
// fragment LDS: b32 word index = row*20 + tig (+4), banks (20*gid+tig)%32
// all distinct).
// asel: 0 -> g_hsh, 1 -> g_attnh. wsel: 0 wq,1 wk,2 wv,3 wo.
// csel: 0 -> Cparam, 1 -> g_projq, 2 -> g_projk, 3 -> g_projv.
// ---------------------------------------------------------------------------
__device__ __forceinline__ void mma_f16(float& d0, float& d1, float& d2, float& d3,
                                        uint32_t a0, uint32_t a1, uint32_t a2, uint32_t a3,
                                        uint32_t b0, uint32_t b1) {
    asm volatile(
        "mma.sync.aligned.m16n8k16.row.col.f32.f16.f16.f32 "
        "{%0,%1,%2,%3}, {%4,%5,%6,%7}, {%8,%9}, {%0,%1,%2,%3};"
        : "+f"(d0), "+f"(d1), "+f"(d2), "+f"(d3)
        : "r"(a0), "r"(a1), "r"(a2), "r"(a3), "r"(b0), "r"(b1));
}

__device__ __forceinline__ void cp16(void* dst, const void* src) {
    uint32_t d = (uint32_t)__cvta_generic_to_shared(dst);
    asm volatile("cp.async.ca.shared.global [%0], [%1], 16;" :: "r"(d), "l"(src));
}

#define LDH     40                      // halves per smem row
#define LDH32   20                      // b32 words per row
#define BKH     32                      // k per iteration (halves)
#define TILEH   (128 * LDH)             // halves per tile
#define STAGES  3
#define GEMM_SMEM_BYTES (STAGES * 2 * TILEH * 2)   // 61,440

__global__ __launch_bounds__(256, 2)
void gemm_h(int asel, int wsel, float* __restrict__ Cparam,
            int M, int N, int K, int csel)
{
    extern __shared__ __half hsm[];
    __half* Asm = hsm;                    // [STAGES][TILEH]
    __half* Bsm = hsm + STAGES * TILEH;

    const __half* A = asel ? g_attnh : g_hsh;
    const __half* W = (wsel == 0) ? g_wqh
                    : (wsel == 1) ? g_wkh
                    : (wsel == 2) ? g_wvh : g_woh;
    float* C = (csel == 0) ? Cparam
             : (csel == 1) ? g_projq
             : (csel == 2) ? g_projk : g_projv;

    const int tid  = threadIdx.x;
    const int lane = tid & 31;
    const int w    = tid >> 5;          // 0..7
    const int wm   = (w >> 2) * 64;     // warp row base: 0 or 64
    const int wn   = (w & 3) * 32;      // warp col base: 0,32,64,96
    const int gid  = lane >> 2;         // 0..7
    const int tig  = lane & 3;          // 0..3

    const int m0 = blockIdx.y * 128;
    const int n0 = blockIdx.x * 128;

    // cp.async mapping: thread -> row = tid>>1 (0..127), base half col
    // c8 = (tid&1)*16; two 16B chunks at c8, c8+8 per matrix per iter.
    const int lrow = tid >> 1;          // 0..127
    const int c8   = (tid & 1) << 4;    // 0 or 16 (halves)

    const __half* Arow = A + (size_t)(m0 + lrow) * K + c8;
    const __half* Wrow = W + (size_t)(n0 + lrow) * K + c8;
    __half* AsmRow = Asm + lrow * LDH + c8;   // + stage*TILEH
    __half* BsmRow = Bsm + lrow * LDH + c8;

    float acc[4][4][4];
#pragma unroll
    for (int mt = 0; mt < 4; mt++)
#pragma unroll
        for (int nt = 0; nt < 4; nt++)
#pragma unroll
            for (int e = 0; e < 4; e++) acc[mt][nt][e] = 0.f;

    const int niter = K >> 5;   // K/32

    // Prologue: stages 0 and 1 in flight.
#pragma unroll
    for (int s = 0; s < 2; s++) {
        const int k0 = s << 5;
        cp16(AsmRow + s * TILEH,     Arow + k0);
        cp16(AsmRow + s * TILEH + 8, Arow + k0 + 8);
        cp16(BsmRow + s * TILEH,     Wrow + k0);
        cp16(BsmRow + s * TILEH + 8, Wrow + k0 + 8);
        asm volatile("cp.async.commit_group;");
    }

    for (int i = 0; i < niter; i++) {
        asm volatile("cp.async.wait_group 1;");
        __syncthreads();   // stage i visible; all warps done with stage i-1

        if (i + 2 < niter) {
            const int s = (i + 2) % STAGES;
            const int k0 = (i + 2) << 5;
            cp16(AsmRow + s * TILEH,     Arow + k0);
            cp16(AsmRow + s * TILEH + 8, Arow + k0 + 8);
            cp16(BsmRow + s * TILEH,     Wrow + k0);
            cp16(BsmRow + s * TILEH + 8, Wrow + k0 + 8);
        }
        asm volatile("cp.async.commit_group;");  // unconditional: count exact

        const uint32_t* Ac = (const uint32_t*)(Asm + (i % STAGES) * TILEH);
        const uint32_t* Bc = (const uint32_t*)(Bsm + (i % STAGES) * TILEH);
#pragma unroll
        for (int ks = 0; ks < 2; ks++) {         // two m16n8k16 k-steps
            const int kw = ks * 8;               // b32 word offset (16 halves)
            uint32_t af[4][4];
#pragma unroll
            for (int mt = 0; mt < 4; mt++) {
                const int rbase = wm + mt * 16 + gid;
                af[mt][0] = Ac[(rbase    ) * LDH32 + kw + tig    ];
                af[mt][1] = Ac[(rbase + 8) * LDH32 + kw + tig    ];
                af[mt][2] = Ac[(rbase    ) * LDH32 + kw + tig + 4];
                af[mt][3] = Ac[(rbase + 8) * LDH32 + kw + tig + 4];
            }
            uint32_t bf[4][2];
#pragma unroll
            for (int nt = 0; nt < 4; nt++) {
                const int nrow = wn + nt * 8 + gid;
                bf[nt][0] = Bc[nrow * LDH32 + kw + tig    ];
                bf[nt][1] = Bc[nrow * LDH32 + kw + tig + 4];
            }
#pragma unroll
            for (int mt = 0; mt < 4; mt++)
#pragma unroll
                for (int nt = 0; nt < 4; nt++)
                    mma_f16(acc[mt][nt][0], acc[mt][nt][1],
                            acc[mt][nt][2], acc[mt][nt][3],
                            af[mt][0], af[mt][1], af[mt][2], af[mt][3],
                            bf[nt][0], bf[nt][1]);
        }
    }

    // Epilogue: (row = gid | gid+8, col = 2*tig | 2*tig+1) per 16x8 subtile.
#pragma unroll
    for (int mt = 0; mt < 4; mt++) {
#pragma unroll
        for (int nt = 0; nt < 4; nt++) {
            const int n = n0 + wn + nt * 8 + 2 * tig;
            const int mA = m0 + wm + mt * 16 + gid;
            float2 v01; v01.x = acc[mt][nt][0]; v01.y = acc[mt][nt][1];
            float2 v23; v23.x = acc[mt][nt][2]; v23.y = acc[mt][nt][3];
            *(float2*)(C + (size_t)mA * N + n)       = v01;
            *(float2*)(C + (size_t)(mA + 8) * N + n) = v23;
        }
    }
}

// ---------------------------------------------------------------------------
// Fused RoPE + transpose for Q, K, V in ONE launch (unchanged - PASSING)
// ---------------------------------------------------------------------------
#define QPAIRS ((size_t)Bq * Sq * Hq * (Dq / 2))
#define KPAIRS ((size_t)Bq * Sq * KVq * (Dq / 2))

__global__ __launch_bounds__(256)
void rope_all(const float* __restrict__ cosp, const float* __restrict__ sinp)
{
    size_t idx = (size_t)blockIdx.x * blockDim.x + threadIdx.x;
    const float* src;
    float* dst;
    int Hh, dorope;
    if (idx < QPAIRS) {
        src = g_projq; dst = g_q; Hh = Hq; dorope = 1;
    } else if (idx < QPAIRS + KPAIRS) {
        idx -= QPAIRS;
        src = g_projk; dst = g_k; Hh = KVq; dorope = 1;
    } else if (idx < QPAIRS + 2 * KPAIRS) {
        idx -= QPAIRS + KPAIRS;
        src = g_projv; dst = g_v; Hh = KVq; dorope = 0;
    } else {
        return;
    }

    const int dpair = (int)(idx % (Dq / 2));
    size_t rest = idx / (Dq / 2);
    const int hh = (int)(rest % Hh);  rest /= Hh;
    const int s  = (int)(rest % Sq);
    const int b  = (int)(rest / Sq);
    const int d  = dpair * 2;

    const size_t srcix = ((size_t)(b * Sq + s) * Hh + hh) * Dq + d;
    float v0 = src[srcix];
    float v1 = src[srcix + 1];
    if (dorope) {
        const float c  = cosp[s * Dq + d];
        const float sn = sinp[s * Dq + d];
        const float t0 = v0 * c - v1 * sn;
        const float t1 = v1 * c + v0 * sn;
        v0 = t0; v1 = t1;
    }
    const size_t o = (((size_t)b * Hh + hh) * Sq + s) * Dq + d;
    dst[o]     = v0;
    dst[o + 1] = v1;
}

// ---------------------------------------------------------------------------
// Flash attention v3 (structure unchanged - PASSING). Output now fp16 to
// g_attnh for the fp16 O-projection.
// ---------------------------------------------------------------------------
#define LDP 130
#define FLASH_FLOATS (64 * LDP + 32 * LDP + 32 * 128)

__global__ __launch_bounds__(256)
void flash_v3()
{
    extern __shared__ float sm[];
    float* Qs = sm;                  // [64][LDP]
    float* Ks = Qs + 64 * LDP;       // [32][LDP]; after scores reused as P[c][r]
    float* Vs = Ks + 32 * LDP;       // [32][128]

    const int qb = blockIdx.x;
    const int h  = blockIdx.y;
    const int b  = blockIdx.z;
    const int kh = h / Gq;
    const int tid = threadIdx.x;
    const int r = tid >> 2;
    const int q = tid & 3;
    const float scale = 0.08838834764831845f;

    const float* Qg = g_q + (((size_t)b * Hq  + h ) * Sq + (size_t)qb * 64) * Dq;
    const float* Kg = g_k + (((size_t)b * KVq + kh) * Sq) * Dq;
    const float* Vg = g_v + (((size_t)b * KVq + kh) * Sq) * Dq;

#pragma unroll
    for (int i = 0; i < 8; i++) {
        const int idx = tid + i * 256;
        const int rr = idx >> 5;
        const int c4 = (idx & 31) << 2;
        float4 v = *(const float4*)(Qg + rr * Dq + c4);
        Qs[rr * LDP + c4 + 0] = v.x;
        Qs[rr * LDP + c4 + 1] = v.y;
        Qs[rr * LDP + c4 + 2] = v.z;
        Qs[rr * LDP + c4 + 3] = v.w;
    }

    float m_i = -INFINITY;
    float l_i = 0.f;
    float o[32];
#pragma unroll
    for (int j = 0; j < 32; j++) o[j] = 0.f;

    const int qr = qb * 64 + r;
    const int ntiles = 2 * qb + 2;

    for (int cb = 0; cb < ntiles; cb++) {
        __syncthreads();
#pragma unroll
        for (int i = 0; i < 4; i++) {
            const int idx = tid + i * 256;
            const int rr = idx >> 5;
            const int c4 = (idx & 31) << 2;
            float4 kv = *(const float4*)(Kg + (size_t)(cb * 32 + rr) * Dq + c4);
            Ks[rr * LDP + c4 + 0] = kv.x;
            Ks[rr * LDP + c4 + 1] = kv.y;
            Ks[rr * LDP + c4 + 2] = kv.z;
            Ks[rr * LDP + c4 + 3] = kv.w;
            float4 vv = *(const float4*)(Vg + (size_t)(cb * 32 + rr) * Dq + c4);
            *(float4*)(Vs + rr * 128 + c4) = vv;
        }
        __syncthreads();

        float s8[8];
#pragma unroll
        for (int j = 0; j < 8; j++) s8[j] = 0.f;
        const float* qrow = Qs + r * LDP;
#pragma unroll 4
        for (int k = 0; k < 128; k++) {
            const float qv = qrow[k];
#pragma unroll
            for (int j = 0; j < 8; j++)
                s8[j] += qv * Ks[(q * 8 + j) * LDP + k];
        }
        __syncthreads();

        float mx = -INFINITY;
#pragma unroll
        for (int j = 0; j < 8; j++) {
            const int kc = cb * 32 + q * 8 + j;
            s8[j] = (kc <= qr) ? s8[j] * scale : -INFINITY;
            mx = fmaxf(mx, s8[j]);
        }
        mx = fmaxf(mx, __shfl_xor_sync(0xffffffffu, mx, 1));
        mx = fmaxf(mx, __shfl_xor_sync(0xffffffffu, mx, 2));
        const float m_new = fmaxf(m_i, mx);
        const float corr  = __expf(m_i - m_new);
        float lsum = 0.f;
#pragma unroll
        for (int j = 0; j < 8; j++) {
            s8[j] = __expf(s8[j] - m_new);
            lsum += s8[j];
        }
        lsum += __shfl_xor_sync(0xffffffffu, lsum, 1);
        lsum += __shfl_xor_sync(0xffffffffu, lsum, 2);
        l_i = l_i * corr + lsum;
        m_i = m_new;
#pragma unroll
        for (int j = 0; j < 32; j++) o[j] *= corr;
#pragma unroll
        for (int j = 0; j < 8; j++)
            Ks[(q * 8 + j) * LDP + r] = s8[j];
        __syncthreads();

        for (int c = 0; c < 32; c++) {
            const float pv = Ks[c * LDP + r];
            const float* vrow = Vs + c * 128 + q * 4;
#pragma unroll
            for (int j = 0; j < 8; j++) {
                float4 v4 = *(const float4*)(vrow + j * 16);
                o[j * 4 + 0] += pv * v4.x;
                o[j * 4 + 1] += pv * v4.y;
                o[j * 4 + 2] += pv * v4.z;
                o[j * 4 + 3] += pv * v4.w;
            }
        }
    }

    // Finalize + write fp16 to g_attnh [B, S, H*D]; d = j*16 + q*4 + e
    const float inv = 1.f / l_i;
    __half* og = g_attnh + ((size_t)(b * Sq + qr) * Hq + h) * Dq + q * 4;
#pragma unroll
    for (int j = 0; j < 8; j++) {
        *(__half2*)(og + j * 16)     = __floats2half2_rn(o[j * 4 + 0] * inv,
                                                         o[j * 4 + 1] * inv);
        *(__half2*)(og + j * 16 + 2) = __floats2half2_rn(o[j * 4 + 2] * inv,
                                                         o[j * 4 + 3] * inv);
    }
}

// ---------------------------------------------------------------------------
// Launcher
// ---------------------------------------------------------------------------
extern "C" void kernel_launch(void* const* d_in, const int* in_sizes, int n_in,
                              void* d_out, int out_size)
{
    const float *hs, *cosp, *sinp, *wq, *wk, *wv, *wo;
    if (in_sizes[0] == Bq * Sq * HIDq) {
        hs   = (const float*)d_in[0];
        cosp = (const float*)d_in[1];
        sinp = (const float*)d_in[2];
        wq   = (const float*)d_in[3];
        wk   = (const float*)d_in[4];
        wv   = (const float*)d_in[5];
        wo   = (const float*)d_in[6];
    } else {  // alphabetical fallback
        cosp = (const float*)d_in[0];
        hs   = (const float*)d_in[1];
        sinp = (const float*)d_in[2];
        wk   = (const float*)d_in[3];
        wo   = (const float*)d_in[4];
        wq   = (const float*)d_in[5];
        wv   = (const float*)d_in[6];
    }
    float* out = (float*)d_out;

    const dim3 blk(256);
    const int M = Bq * Sq;          // 4096
    const int NQ = Hq * Dq;         // 4096
    const int NKV = KVq * Dq;       // 1024

    // fp32 -> fp16 input conversion
    {
        size_t n4;
        n4 = (size_t)Bq * Sq * HIDq / 4;
        to_half<<<(unsigned)((n4 + 255) / 256), 256>>>((const float4*)hs, 0, n4);
        n4 = (size_t)Hq * Dq * HIDq / 4;
        to_half<<<(unsigned)((n4 + 255) / 256), 256>>>((const float4*)wq, 1, n4);
        n4 = (size_t)KVq * Dq * HIDq / 4;
        to_half<<<(unsigned)((n4 + 255) / 256), 256>>>((const float4*)wk, 2, n4);
        to_half<<<(unsigned)((n4 + 255) / 256), 256>>>((const float4*)wv, 3, n4);
        n4 = (size_t)HIDq * Hq * Dq / 4;
        to_half<<<(unsigned)((n4 + 255) / 256), 256>>>((const float4*)wo, 4, n4);
    }

    cudaFuncSetAttribute(gemm_h, cudaFuncAttributeMaxDynamicSharedMemorySize,
                         GEMM_SMEM_BYTES);

    // Projections
    gemm_h<<<dim3(NQ / 128, M / 128), blk, GEMM_SMEM_BYTES>>>(0, 0, nullptr, M, NQ, HIDq, 1);
    gemm_h<<<dim3(NKV / 128, M / 128), blk, GEMM_SMEM_BYTES>>>(0, 1, nullptr, M, NKV, HIDq, 2);
    gemm_h<<<dim3(NKV / 128, M / 128), blk, GEMM_SMEM_BYTES>>>(0, 2, nullptr, M, NKV, HIDq, 3);

    // Fused RoPE/transpose for Q,K,V
    {
        size_t total = QPAIRS + 2 * KPAIRS;
        rope_all<<<(unsigned)((total + 255) / 256), 256>>>(cosp, sinp);
    }

    // Flash attention v3 -> g_attnh (fp16)
    const int smem_bytes = FLASH_FLOATS * (int)sizeof(float);  // 66,304
    cudaFuncSetAttribute(flash_v3, cudaFuncAttributeMaxDynamicSharedMemorySize,
                         smem_bytes);
    flash_v3<<<dim3(Sq / 64, Hq, Bq), blk, smem_bytes>>>();

    // Output projection: out = g_attnh @ wo^T
    gemm_h<<<dim3(HIDq / 128, M / 128), blk, GEMM_SMEM_BYTES>>>(1, 3, out, M, HIDq, NQ, 0);
}